// round 11
// baseline (speedup 1.0000x reference)
#include <cuda_runtime.h>
#include <stdint.h>

// out = cos(X @ Win^T + theta) @ Wout^T      X:[262144,64] fp32
// fp16 m16n8k16 single-pass (11-bit mantissa == tf32 -> rel_err ~4e-4).
// R11: R10 fp16 kernel reshaped for occupancy: 128-thread CTAs,
// __launch_bounds__(128,5) (<=102 regs -> 20 warps/SM), X streamed per
// k-pair so peak liveness ~95 regs (t64 + xj16 + misc). Layout algebra
// unchanged (natural Win, ginv/word-scatter Wout -> STG.128 outputs).

#define NTOK   (32 * 8192)
#define TILE_T 128                 // tokens per CTA (4 warps x 32)
#define NCTAS  (NTOK / TILE_T)     // 2048
#define PITCH4 12                  // uint4 per smem weight row (12%8==4 -> conflict-free)

__device__ __forceinline__ uint32_t pack_h2(float lo, float hi) {
    uint32_t d;
    asm("cvt.rn.f16x2.f32 %0, %1, %2;" : "=r"(d) : "f"(hi), "f"(lo));
    return d;
}

__device__ __forceinline__ void mma16(float* c, uint32_t a0, uint32_t a1, uint32_t a2, uint32_t a3,
                                      uint32_t b0, uint32_t b1) {
    asm volatile(
        "mma.sync.aligned.m16n8k16.row.col.f32.f16.f16.f32 "
        "{%0,%1,%2,%3}, {%4,%5,%6,%7}, {%8,%9}, {%0,%1,%2,%3};"
        : "+f"(c[0]), "+f"(c[1]), "+f"(c[2]), "+f"(c[3])
        : "r"(a0), "r"(a1), "r"(a2), "r"(a3), "r"(b0), "r"(b1));
}

__device__ __forceinline__ float4 ldcs4(const float* p) {
    float4 v;
    asm volatile("ld.global.cs.v4.f32 {%0,%1,%2,%3}, [%4];"
                 : "=f"(v.x), "=f"(v.y), "=f"(v.z), "=f"(v.w) : "l"(p));
    return v;
}
__device__ __forceinline__ void stcs4(float* p, float a, float b, float c, float d) {
    asm volatile("st.global.cs.v4.f32 [%0], {%1,%2,%3,%4};"
                 :: "l"(p), "f"(a), "f"(b), "f"(c), "f"(d));
}

// Wout row scramble: slot row s holds logical row so that thread stores coalesce.
__device__ __forceinline__ int ginv_off(int p) {
    return ((p & 2) >> 1) * 8 + ((p >> 2) & 3) * 2 + (p & 1);
}

__global__ void __launch_bounds__(128, 5)
quantum_fp16_kernel(const float* __restrict__ x,
                    const float* __restrict__ Win,    // [64][64]
                    const float* __restrict__ theta,  // [64]
                    const float* __restrict__ Wout,   // [64][64]
                    float* __restrict__ out)
{
    // fp16 weights in LDS.128 quads (see R10 derivation).
    __shared__ uint32_t sWin[64 * PITCH4 * 4];
    __shared__ uint32_t sWout[64 * PITCH4 * 4];
    __shared__ float    sTh[64];

    const int tid = threadIdx.x;

    // ---- Fill Win (natural words, quad-grouped) ----
    for (int idx = tid; idx < 1024; idx += 128) {
        const int r = idx >> 4, c = idx & 15;       // float4 c: cols 4c..4c+3
        float4 w = ldcs4(Win + r * 64 + c * 4);
        const int j = c >> 2, tcw = c & 3;
        uint32_t* quad = &sWin[(r * PITCH4 + (j >> 1) * 4 + tcw) * 4];
        quad[(j & 1) * 2 + 0] = pack_h2(w.x, w.y);
        quad[(j & 1) * 2 + 1] = pack_h2(w.z, w.w);
    }
    // ---- Fill Wout (row scramble + word scatter into quads) ----
    for (int idx = tid; idx < 1024; idx += 128) {
        const int r = idx >> 4, c = idx & 15;
        float4 w = ldcs4(Wout + r * 64 + c * 4);
        const int s = (r & ~15) | ginv_off(r & 15);
        uint32_t ww0 = pack_h2(w.x, w.y), ww1 = pack_h2(w.z, w.w);
#pragma unroll
        for (int d = 0; d < 2; d++) {
            const int wv = 2 * c + d;               // word index: cols 2wv, 2wv+1
            const int j2 = wv >> 3, v = wv & 7;
            const int tcw  = (v < 4) ? v : v - 4;
            const int elem = (j2 & 1) * 2 + ((v < 4) ? 0 : 1);
            sWout[(s * PITCH4 + (j2 >> 1) * 4 + tcw) * 4 + elem] = d ? ww1 : ww0;
        }
    }
    if (tid < 64) sTh[tid] = theta[tid];
    __syncthreads();

    const int lane = tid & 31;
    const int warp = tid >> 5;    // 0..3
    const int gr   = lane >> 2;
    const int tc   = lane & 3;

    const int tok0 = blockIdx.x * TILE_T + warp * 32;   // 32 tokens (2 m-tiles) per warp
    const float* px = x + (size_t)(tok0 + gr) * 64 + tc * 4;

    // ---- Phase 1: GEMM1 (fp16 k16), X streamed per k-pair jp ----
    float t[2][8][4];
#pragma unroll
    for (int mt = 0; mt < 2; mt++)
#pragma unroll
        for (int nt = 0; nt < 8; nt++)
#pragma unroll
            for (int i = 0; i < 4; i++) t[mt][nt][i] = 0.f;

#pragma unroll
    for (int jp = 0; jp < 2; jp++) {
        uint32_t xj[2][2][4];   // [mt][jj][a0..a3], chunks j = 2jp+jj
#pragma unroll
        for (int mt = 0; mt < 2; mt++) {
#pragma unroll
            for (int jj = 0; jj < 2; jj++) {
                const int j = 2 * jp + jj;
                float4 v0 = ldcs4(px + (mt * 16) * 64 + j * 16);
                float4 v1 = ldcs4(px + (mt * 16 + 8) * 64 + j * 16);
                xj[mt][jj][0] = pack_h2(v0.x, v0.y);   // row gr,   k-lo
                xj[mt][jj][1] = pack_h2(v1.x, v1.y);   // row gr+8, k-lo
                xj[mt][jj][2] = pack_h2(v0.z, v0.w);   // row gr,   k-hi
                xj[mt][jj][3] = pack_h2(v1.z, v1.w);   // row gr+8, k-hi
            }
        }
#pragma unroll
        for (int nt = 0; nt < 8; nt++) {
            const uint4 b = *(const uint4*)&sWin[((8 * nt + gr) * PITCH4 + jp * 4 + tc) * 4];
#pragma unroll
            for (int mt = 0; mt < 2; mt++) {
                mma16(t[mt][nt], xj[mt][0][0], xj[mt][0][1],
                                 xj[mt][0][2], xj[mt][0][3], b.x, b.y);
                mma16(t[mt][nt], xj[mt][1][0], xj[mt][1][1],
                                 xj[mt][1][2], xj[mt][1][3], b.z, b.w);
            }
        }
    }

    // ---- Phase 1.5: q = cos(t + theta); pack straight into GEMM2 A-frags ----
    uint32_t a2f[2][4][4];  // [mt][j2][a0..a3]
#pragma unroll
    for (int nt = 0; nt < 8; nt++) {
        const float2 tb = *(const float2*)&sTh[8 * nt + 2 * tc];
        const int j2 = nt >> 1, e = nt & 1;
#pragma unroll
        for (int mt = 0; mt < 2; mt++) {
            float f0 = __cosf(t[mt][nt][0] + tb.x);
            float f1 = __cosf(t[mt][nt][1] + tb.y);
            float f2 = __cosf(t[mt][nt][2] + tb.x);
            float f3 = __cosf(t[mt][nt][3] + tb.y);
            a2f[mt][j2][2 * e + 0] = pack_h2(f0, f1);
            a2f[mt][j2][2 * e + 1] = pack_h2(f2, f3);
        }
    }
    // t dead here.

    // ---- Phase 2: GEMM2 per output-tile pair, store STG.128 immediately ----
#pragma unroll
    for (int np = 0; np < 4; np++) {
        float acc[2][2][4];
#pragma unroll
        for (int mt = 0; mt < 2; mt++)
#pragma unroll
            for (int e = 0; e < 2; e++)
#pragma unroll
                for (int i = 0; i < 4; i++) acc[mt][e][i] = 0.f;

#pragma unroll
        for (int jp = 0; jp < 2; jp++) {
#pragma unroll
            for (int e = 0; e < 2; e++) {
                const int nt2 = 2 * np + e;
                const uint4 b2 = *(const uint4*)&sWout[((8 * nt2 + gr) * PITCH4 + jp * 4 + tc) * 4];
#pragma unroll
                for (int mt = 0; mt < 2; mt++) {
                    mma16(acc[mt][e], a2f[mt][2 * jp][0], a2f[mt][2 * jp][1],
                                      a2f[mt][2 * jp][2], a2f[mt][2 * jp][3], b2.x, b2.y);
                    mma16(acc[mt][e], a2f[mt][2 * jp + 1][0], a2f[mt][2 * jp + 1][1],
                                      a2f[mt][2 * jp + 1][2], a2f[mt][2 * jp + 1][3], b2.z, b2.w);
                }
            }
        }

        const int col = np * 16 + tc * 4;
#pragma unroll
        for (int mt = 0; mt < 2; mt++) {
            const size_t r0 = (size_t)(tok0 + mt * 16 + gr);
            stcs4(out + r0 * 64 + col,
                  acc[mt][0][0], acc[mt][0][1], acc[mt][1][0], acc[mt][1][1]);
            stcs4(out + (r0 + 8) * 64 + col,
                  acc[mt][0][2], acc[mt][0][3], acc[mt][1][2], acc[mt][1][3]);
        }
    }
}

extern "C" void kernel_launch(void* const* d_in, const int* in_sizes, int n_in,
                              void* d_out, int out_size) {
    const float* x     = (const float*)d_in[0];
    const float* W_in  = (const float*)d_in[1];
    const float* theta = (const float*)d_in[2];
    const float* W_out = (const float*)d_in[3];
    float* out = (float*)d_out;

    quantum_fp16_kernel<<<NCTAS, 128>>>(x, W_in, theta, W_out, out);
}

// round 12
// speedup vs baseline: 1.0798x; 1.0798x over previous
#include <cuda_runtime.h>
#include <stdint.h>

// out = cos(X @ Win^T + theta) @ Wout^T      X:[262144,64] fp32
// fp16 m16n8k16 single-pass (11-bit mantissa -> rel_err ~4e-4).
// R12: persistent CTAs (grid 296, ~3.5 tiles each) + cross-tile register
// prefetch of X (two 8xLDG.128 batches hidden under GEMM1/GEMM2) + GEMM1
// split into nt-halves (t: 32 regs) to fit the 128-reg/16-warp plateau.
// Layout algebra unchanged from R10 (natural Win quads, ginv/word-scatter
// Wout quads -> STG.128 outputs).

#define NTOK   (32 * 8192)
#define TILE_T 256                 // tokens per tile (8 warps x 32)
#define NTILES (NTOK / TILE_T)     // 1024
#define GRIDSZ 296                 // 2 CTAs/SM persistent
#define PITCH4 12                  // uint4 per smem weight row (12%8==4 -> conflict-free)

__device__ __forceinline__ uint32_t pack_h2(float lo, float hi) {
    uint32_t d;
    asm("cvt.rn.f16x2.f32 %0, %1, %2;" : "=r"(d) : "f"(hi), "f"(lo));
    return d;
}

__device__ __forceinline__ void mma16(float* c, uint32_t a0, uint32_t a1, uint32_t a2, uint32_t a3,
                                      uint32_t b0, uint32_t b1) {
    asm volatile(
        "mma.sync.aligned.m16n8k16.row.col.f32.f16.f16.f32 "
        "{%0,%1,%2,%3}, {%4,%5,%6,%7}, {%8,%9}, {%0,%1,%2,%3};"
        : "+f"(c[0]), "+f"(c[1]), "+f"(c[2]), "+f"(c[3])
        : "r"(a0), "r"(a1), "r"(a2), "r"(a3), "r"(b0), "r"(b1));
}

__device__ __forceinline__ float4 ldcs4(const float* p) {
    float4 v;
    asm volatile("ld.global.cs.v4.f32 {%0,%1,%2,%3}, [%4];"
                 : "=f"(v.x), "=f"(v.y), "=f"(v.z), "=f"(v.w) : "l"(p));
    return v;
}
__device__ __forceinline__ void stcs4(float* p, float a, float b, float c, float d) {
    asm volatile("st.global.cs.v4.f32 [%0], {%1,%2,%3,%4};"
                 :: "l"(p), "f"(a), "f"(b), "f"(c), "f"(d));
}

// Wout row scramble: slot row s holds logical row so thread stores coalesce.
__device__ __forceinline__ int ginv_off(int p) {
    return ((p & 2) >> 1) * 8 + ((p >> 2) & 3) * 2 + (p & 1);
}

__global__ void __launch_bounds__(256, 2)
quantum_fp16_persist(const float* __restrict__ x,
                     const float* __restrict__ Win,    // [64][64]
                     const float* __restrict__ theta,  // [64]
                     const float* __restrict__ Wout,   // [64][64]
                     float* __restrict__ out)
{
    __shared__ uint32_t sWin[64 * PITCH4 * 4];
    __shared__ uint32_t sWout[64 * PITCH4 * 4];
    __shared__ float    sTh[64];

    const int tid  = threadIdx.x;
    const int lane = tid & 31;
    const int warp = tid >> 5;    // 0..7
    const int gr   = lane >> 2;
    const int tc   = lane & 3;
    const int wtok = warp * 32;   // warp's token offset within a tile

    int tile = blockIdx.x;

    // ---- Issue first tile's X loads FIRST (overlaps weight-fill DRAM wait) ----
    float4 vA[8], vB[8];   // batch A = m-tile 0, batch B = m-tile 1 (8 LDG.128 each)
    {
        const float* p0 = x + (size_t)(tile * TILE_T + wtok + gr) * 64 + tc * 4;
#pragma unroll
        for (int j = 0; j < 4; j++) {
            vA[2 * j + 0] = ldcs4(p0 + j * 16);
            vA[2 * j + 1] = ldcs4(p0 + j * 16 + 8 * 64);
        }
#pragma unroll
        for (int j = 0; j < 4; j++) {
            vB[2 * j + 0] = ldcs4(p0 + j * 16 + 16 * 64);
            vB[2 * j + 1] = ldcs4(p0 + j * 16 + 24 * 64);
        }
    }

    // ---- Weight fill (plain cached loads; reused across the tile loop) ----
    for (int idx = tid; idx < 1024; idx += 256) {
        const int r = idx >> 4, c = idx & 15;
        float4 w = *(const float4*)(Win + r * 64 + c * 4);
        const int j = c >> 2, tcw = c & 3;
        uint32_t* quad = &sWin[(r * PITCH4 + (j >> 1) * 4 + tcw) * 4];
        quad[(j & 1) * 2 + 0] = pack_h2(w.x, w.y);
        quad[(j & 1) * 2 + 1] = pack_h2(w.z, w.w);
    }
    for (int idx = tid; idx < 1024; idx += 256) {
        const int r = idx >> 4, c = idx & 15;
        float4 w = *(const float4*)(Wout + r * 64 + c * 4);
        const int s = (r & ~15) | ginv_off(r & 15);
        uint32_t ww0 = pack_h2(w.x, w.y), ww1 = pack_h2(w.z, w.w);
#pragma unroll
        for (int d = 0; d < 2; d++) {
            const int wv = 2 * c + d;
            const int j2 = wv >> 3, v = wv & 7;
            const int tcw  = (v < 4) ? v : v - 4;
            const int elem = (j2 & 1) * 2 + ((v < 4) ? 0 : 1);
            sWout[(s * PITCH4 + (j2 >> 1) * 4 + tcw) * 4 + elem] = d ? ww1 : ww0;
        }
    }
    if (tid < 64) sTh[tid] = theta[tid];
    __syncthreads();

    // ---- Persistent tile loop with cross-tile prefetch ----
    for (; tile < NTILES; tile += GRIDSZ) {
        const int tok0 = tile * TILE_T + wtok;
        int nxt = tile + GRIDSZ;
        if (nxt >= NTILES) nxt = tile;            // clamp: loads stay valid, results unused
        const float* pn = x + (size_t)(nxt * TILE_T + wtok + gr) * 64 + tc * 4;

        // Pack current tile's fragments (vA/vB die here)
        uint32_t xa[2][4][4];
#pragma unroll
        for (int j = 0; j < 4; j++) {
            xa[0][j][0] = pack_h2(vA[2 * j].x,     vA[2 * j].y);
            xa[0][j][1] = pack_h2(vA[2 * j + 1].x, vA[2 * j + 1].y);
            xa[0][j][2] = pack_h2(vA[2 * j].z,     vA[2 * j].w);
            xa[0][j][3] = pack_h2(vA[2 * j + 1].z, vA[2 * j + 1].w);
            xa[1][j][0] = pack_h2(vB[2 * j].x,     vB[2 * j].y);
            xa[1][j][1] = pack_h2(vB[2 * j + 1].x, vB[2 * j + 1].y);
            xa[1][j][2] = pack_h2(vB[2 * j].z,     vB[2 * j].w);
            xa[1][j][3] = pack_h2(vB[2 * j + 1].z, vB[2 * j + 1].w);
        }

        // Prefetch batch A for next tile (lands during GEMM1/cos)
#pragma unroll
        for (int j = 0; j < 4; j++) {
            vA[2 * j + 0] = ldcs4(pn + j * 16);
            vA[2 * j + 1] = ldcs4(pn + j * 16 + 8 * 64);
        }

        // ---- GEMM1 + cos, split into two nt-halves (t: 32 regs) ----
        uint32_t a2f[2][4][4];
#pragma unroll
        for (int h = 0; h < 2; h++) {
            float t[2][4][4];
#pragma unroll
            for (int mt = 0; mt < 2; mt++)
#pragma unroll
                for (int n = 0; n < 4; n++)
#pragma unroll
                    for (int i = 0; i < 4; i++) t[mt][n][i] = 0.f;

#pragma unroll
            for (int jp = 0; jp < 2; jp++) {
#pragma unroll
                for (int n = 0; n < 4; n++) {
                    const int nt = 4 * h + n;
                    const uint4 b = *(const uint4*)&sWin[((8 * nt + gr) * PITCH4 + jp * 4 + tc) * 4];
#pragma unroll
                    for (int mt = 0; mt < 2; mt++) {
                        mma16(t[mt][n], xa[mt][2 * jp][0], xa[mt][2 * jp][1],
                                        xa[mt][2 * jp][2], xa[mt][2 * jp][3], b.x, b.y);
                        mma16(t[mt][n], xa[mt][2 * jp + 1][0], xa[mt][2 * jp + 1][1],
                                        xa[mt][2 * jp + 1][2], xa[mt][2 * jp + 1][3], b.z, b.w);
                    }
                }
            }
#pragma unroll
            for (int n = 0; n < 4; n++) {
                const int nt = 4 * h + n;
                const float2 tb = *(const float2*)&sTh[8 * nt + 2 * tc];
                const int j2 = nt >> 1, e = nt & 1;
#pragma unroll
                for (int mt = 0; mt < 2; mt++) {
                    float f0 = __cosf(t[mt][n][0] + tb.x);
                    float f1 = __cosf(t[mt][n][1] + tb.y);
                    float f2 = __cosf(t[mt][n][2] + tb.x);
                    float f3 = __cosf(t[mt][n][3] + tb.y);
                    a2f[mt][j2][2 * e + 0] = pack_h2(f0, f1);
                    a2f[mt][j2][2 * e + 1] = pack_h2(f2, f3);
                }
            }
        }
        // xa dead. Prefetch batch B for next tile (lands during GEMM2/stores).
#pragma unroll
        for (int j = 0; j < 4; j++) {
            vB[2 * j + 0] = ldcs4(pn + j * 16 + 16 * 64);
            vB[2 * j + 1] = ldcs4(pn + j * 16 + 24 * 64);
        }

        // ---- GEMM2 per output-tile pair, STG.128 immediately ----
#pragma unroll
        for (int np = 0; np < 4; np++) {
            float acc[2][2][4];
#pragma unroll
            for (int mt = 0; mt < 2; mt++)
#pragma unroll
                for (int e = 0; e < 2; e++)
#pragma unroll
                    for (int i = 0; i < 4; i++) acc[mt][e][i] = 0.f;

#pragma unroll
            for (int jp = 0; jp < 2; jp++) {
#pragma unroll
                for (int e = 0; e < 2; e++) {
                    const int nt2 = 2 * np + e;
                    const uint4 b2 = *(const uint4*)&sWout[((8 * nt2 + gr) * PITCH4 + jp * 4 + tc) * 4];
#pragma unroll
                    for (int mt = 0; mt < 2; mt++) {
                        mma16(acc[mt][e], a2f[mt][2 * jp][0], a2f[mt][2 * jp][1],
                                          a2f[mt][2 * jp][2], a2f[mt][2 * jp][3], b2.x, b2.y);
                        mma16(acc[mt][e], a2f[mt][2 * jp + 1][0], a2f[mt][2 * jp + 1][1],
                                          a2f[mt][2 * jp + 1][2], a2f[mt][2 * jp + 1][3], b2.z, b2.w);
                    }
                }
            }

            const int col = np * 16 + tc * 4;
#pragma unroll
            for (int mt = 0; mt < 2; mt++) {
                const size_t r0 = (size_t)(tok0 + mt * 16 + gr);
                stcs4(out + r0 * 64 + col,
                      acc[mt][0][0], acc[mt][0][1], acc[mt][1][0], acc[mt][1][1]);
                stcs4(out + (r0 + 8) * 64 + col,
                      acc[mt][0][2], acc[mt][0][3], acc[mt][1][2], acc[mt][1][3]);
            }
        }
    }
}

extern "C" void kernel_launch(void* const* d_in, const int* in_sizes, int n_in,
                              void* d_out, int out_size) {
    const float* x     = (const float*)d_in[0];
    const float* W_in  = (const float*)d_in[1];
    const float* theta = (const float*)d_in[2];
    const float* W_out = (const float*)d_in[3];
    float* out = (float*)d_out;

    quantum_fp16_persist<<<GRIDSZ, 256>>>(x, W_in, theta, W_out, out);
}

// round 13
// speedup vs baseline: 1.2793x; 1.1848x over previous
#include <cuda_runtime.h>
#include <stdint.h>

// out = cos(X @ Win^T + theta) @ Wout^T      X:[262144,64] fp32
// fp16 m16n8k16 single-pass (11-bit mantissa -> rel_err ~4e-4).
// R13: persistent warp-level work stealing. 296 CTAs x 8 warps steal
// 32-token chunks from a global counter (reset by a prologue kernel each
// launch). Weight fill amortized 296x; no per-tile CTA syncs; warps desync
// across load/MMA/cos phases. Body identical to R10 (best: 33.3us).

#define NTOK   (32 * 8192)
#define NCHUNK (NTOK / 32)         // 8192 chunks of 32 tokens
#define GRIDSZ 296                 // 2 CTAs/SM persistent
#define PITCH4 12                  // uint4 per smem weight row (12%8==4 -> conflict-free)

__device__ unsigned g_ctr;

__global__ void reset_ctr_kernel() { g_ctr = 0u; }

__device__ __forceinline__ uint32_t pack_h2(float lo, float hi) {
    uint32_t d;
    asm("cvt.rn.f16x2.f32 %0, %1, %2;" : "=r"(d) : "f"(hi), "f"(lo));
    return d;
}

__device__ __forceinline__ void mma16(float* c, uint32_t a0, uint32_t a1, uint32_t a2, uint32_t a3,
                                      uint32_t b0, uint32_t b1) {
    asm volatile(
        "mma.sync.aligned.m16n8k16.row.col.f32.f16.f16.f32 "
        "{%0,%1,%2,%3}, {%4,%5,%6,%7}, {%8,%9}, {%0,%1,%2,%3};"
        : "+f"(c[0]), "+f"(c[1]), "+f"(c[2]), "+f"(c[3])
        : "r"(a0), "r"(a1), "r"(a2), "r"(a3), "r"(b0), "r"(b1));
}

__device__ __forceinline__ float4 ldcs4(const float* p) {
    float4 v;
    asm volatile("ld.global.cs.v4.f32 {%0,%1,%2,%3}, [%4];"
                 : "=f"(v.x), "=f"(v.y), "=f"(v.z), "=f"(v.w) : "l"(p));
    return v;
}
__device__ __forceinline__ void stcs4(float* p, float a, float b, float c, float d) {
    asm volatile("st.global.cs.v4.f32 [%0], {%1,%2,%3,%4};"
                 :: "l"(p), "f"(a), "f"(b), "f"(c), "f"(d));
}

// Wout row scramble: slot row s holds logical row so thread stores coalesce.
__device__ __forceinline__ int ginv_off(int p) {
    return ((p & 2) >> 1) * 8 + ((p >> 2) & 3) * 2 + (p & 1);
}

__global__ void __launch_bounds__(256, 2)
quantum_fp16_steal(const float* __restrict__ x,
                   const float* __restrict__ Win,    // [64][64]
                   const float* __restrict__ theta,  // [64]
                   const float* __restrict__ Wout,   // [64][64]
                   float* __restrict__ out)
{
    __shared__ uint32_t sWin[64 * PITCH4 * 4];
    __shared__ uint32_t sWout[64 * PITCH4 * 4];
    __shared__ float    sTh[64];

    const int tid  = threadIdx.x;
    const int lane = tid & 31;
    const int gr   = lane >> 2;
    const int tc   = lane & 3;

    // ---- Weight fill (plain cached loads; amortized over ~27 chunks/warp) ----
    for (int idx = tid; idx < 1024; idx += 256) {
        const int r = idx >> 4, c = idx & 15;
        float4 w = *(const float4*)(Win + r * 64 + c * 4);
        const int j = c >> 2, tcw = c & 3;
        uint32_t* quad = &sWin[(r * PITCH4 + (j >> 1) * 4 + tcw) * 4];
        quad[(j & 1) * 2 + 0] = pack_h2(w.x, w.y);
        quad[(j & 1) * 2 + 1] = pack_h2(w.z, w.w);
    }
    for (int idx = tid; idx < 1024; idx += 256) {
        const int r = idx >> 4, c = idx & 15;
        float4 w = *(const float4*)(Wout + r * 64 + c * 4);
        const int s = (r & ~15) | ginv_off(r & 15);
        uint32_t ww0 = pack_h2(w.x, w.y), ww1 = pack_h2(w.z, w.w);
#pragma unroll
        for (int d = 0; d < 2; d++) {
            const int wv = 2 * c + d;
            const int j2 = wv >> 3, v = wv & 7;
            const int tcw  = (v < 4) ? v : v - 4;
            const int elem = (j2 & 1) * 2 + ((v < 4) ? 0 : 1);
            sWout[(s * PITCH4 + (j2 >> 1) * 4 + tcw) * 4 + elem] = d ? ww1 : ww0;
        }
    }
    if (tid < 64) sTh[tid] = theta[tid];
    __syncthreads();

    // ---- Per-warp persistent work-stealing loop (no further CTA syncs) ----
    unsigned cur = 0;
    if (lane == 0) cur = atomicAdd(&g_ctr, 1u);
    cur = __shfl_sync(0xffffffffu, cur, 0);

    while (cur < NCHUNK) {
        const size_t tok0 = (size_t)cur * 32;
        const float* p0 = x + (tok0 + gr) * 64 + tc * 4;

        // Front-batched x loads (16 x LDG.128)
        float4 v[16];
#pragma unroll
        for (int mt = 0; mt < 2; mt++)
#pragma unroll
            for (int j = 0; j < 4; j++) {
                v[mt * 8 + 2 * j + 0] = ldcs4(p0 + (mt * 16) * 64 + j * 16);
                v[mt * 8 + 2 * j + 1] = ldcs4(p0 + (mt * 16 + 8) * 64 + j * 16);
            }

        // Steal next chunk now — ATOMG latency hides under the LDG waits.
        unsigned nxt = 0;
        if (lane == 0) nxt = atomicAdd(&g_ctr, 1u);
        nxt = __shfl_sync(0xffffffffu, nxt, 0);

        // Pack A-fragments
        uint32_t xa[2][4][4];
#pragma unroll
        for (int mt = 0; mt < 2; mt++)
#pragma unroll
            for (int j = 0; j < 4; j++) {
                const float4 v0 = v[mt * 8 + 2 * j + 0];
                const float4 v1 = v[mt * 8 + 2 * j + 1];
                xa[mt][j][0] = pack_h2(v0.x, v0.y);   // row gr,   k-lo
                xa[mt][j][1] = pack_h2(v1.x, v1.y);   // row gr+8, k-lo
                xa[mt][j][2] = pack_h2(v0.z, v0.w);   // row gr,   k-hi
                xa[mt][j][3] = pack_h2(v1.z, v1.w);   // row gr+8, k-hi
            }

        // ---- GEMM1 (fp16 k16), 16 independent accumulator chains ----
        float t[2][8][4];
#pragma unroll
        for (int mt = 0; mt < 2; mt++)
#pragma unroll
            for (int nt = 0; nt < 8; nt++)
#pragma unroll
                for (int i = 0; i < 4; i++) t[mt][nt][i] = 0.f;

#pragma unroll
        for (int jp = 0; jp < 2; jp++) {
#pragma unroll
            for (int nt = 0; nt < 8; nt++) {
                const uint4 b = *(const uint4*)&sWin[((8 * nt + gr) * PITCH4 + jp * 4 + tc) * 4];
#pragma unroll
                for (int mt = 0; mt < 2; mt++) {
                    mma16(t[mt][nt], xa[mt][2 * jp][0], xa[mt][2 * jp][1],
                                     xa[mt][2 * jp][2], xa[mt][2 * jp][3], b.x, b.y);
                    mma16(t[mt][nt], xa[mt][2 * jp + 1][0], xa[mt][2 * jp + 1][1],
                                     xa[mt][2 * jp + 1][2], xa[mt][2 * jp + 1][3], b.z, b.w);
                }
            }
        }

        // ---- q = cos(t + theta); pack straight into GEMM2 A-frags ----
        uint32_t a2f[2][4][4];
#pragma unroll
        for (int nt = 0; nt < 8; nt++) {
            const float2 tb = *(const float2*)&sTh[8 * nt + 2 * tc];
            const int j2 = nt >> 1, e = nt & 1;
#pragma unroll
            for (int mt = 0; mt < 2; mt++) {
                float f0 = __cosf(t[mt][nt][0] + tb.x);
                float f1 = __cosf(t[mt][nt][1] + tb.y);
                float f2 = __cosf(t[mt][nt][2] + tb.x);
                float f3 = __cosf(t[mt][nt][3] + tb.y);
                a2f[mt][j2][2 * e + 0] = pack_h2(f0, f1);
                a2f[mt][j2][2 * e + 1] = pack_h2(f2, f3);
            }
        }

        // ---- GEMM2 per output-tile pair, STG.128 immediately ----
#pragma unroll
        for (int np = 0; np < 4; np++) {
            float acc[2][2][4];
#pragma unroll
            for (int mt = 0; mt < 2; mt++)
#pragma unroll
                for (int e = 0; e < 2; e++)
#pragma unroll
                    for (int i = 0; i < 4; i++) acc[mt][e][i] = 0.f;

#pragma unroll
            for (int jp = 0; jp < 2; jp++) {
#pragma unroll
                for (int e = 0; e < 2; e++) {
                    const int nt2 = 2 * np + e;
                    const uint4 b2 = *(const uint4*)&sWout[((8 * nt2 + gr) * PITCH4 + jp * 4 + tc) * 4];
#pragma unroll
                    for (int mt = 0; mt < 2; mt++) {
                        mma16(acc[mt][e], a2f[mt][2 * jp][0], a2f[mt][2 * jp][1],
                                          a2f[mt][2 * jp][2], a2f[mt][2 * jp][3], b2.x, b2.y);
                        mma16(acc[mt][e], a2f[mt][2 * jp + 1][0], a2f[mt][2 * jp + 1][1],
                                          a2f[mt][2 * jp + 1][2], a2f[mt][2 * jp + 1][3], b2.z, b2.w);
                    }
                }
            }

            const int col = np * 16 + tc * 4;
#pragma unroll
            for (int mt = 0; mt < 2; mt++) {
                const size_t r0 = tok0 + mt * 16 + gr;
                stcs4(out + r0 * 64 + col,
                      acc[mt][0][0], acc[mt][0][1], acc[mt][1][0], acc[mt][1][1]);
                stcs4(out + (r0 + 8) * 64 + col,
                      acc[mt][0][2], acc[mt][0][3], acc[mt][1][2], acc[mt][1][3]);
            }
        }

        cur = nxt;
    }
}

extern "C" void kernel_launch(void* const* d_in, const int* in_sizes, int n_in,
                              void* d_out, int out_size) {
    const float* x     = (const float*)d_in[0];
    const float* W_in  = (const float*)d_in[1];
    const float* theta = (const float*)d_in[2];
    const float* W_out = (const float*)d_in[3];
    float* out = (float*)d_out;

    reset_ctr_kernel<<<1, 1>>>();
    quantum_fp16_steal<<<GRIDSZ, 256>>>(x, W_in, theta, W_out, out);
}